// round 7
// baseline (speedup 1.0000x reference)
#include <cuda_runtime.h>
#include <cuda.h>
#include <stdint.h>
#include <math.h>

#define B_ 8
#define T_ 2048
#define D_ 768
#define KC 32
#define NSTAGE 3
#define LDS_ 36                       // padded row stride (floats): conflict-free frags
#define TILE_FLOATS (128 * LDS_)      // 4608 floats per operand tile
#define SMEM_DYN (2 * NSTAGE * TILE_FLOATS * 4)  // 3 stages x (A + B) = 110592 B

// Scratch: scores->(in-place) weights; transposed tf32 X; converted row-major X.
__device__ float g_S[(size_t)B_ * T_ * T_];
__device__ float g_Xt[(size_t)B_ * D_ * T_];
__device__ float g_Xc[(size_t)B_ * T_ * D_];

__device__ __forceinline__ uint32_t f2tf32(float v) {
    uint32_t o;
    asm("cvt.rna.tf32.f32 %0, %1;" : "=r"(o) : "f"(v));
    return o;
}

__device__ __forceinline__ void mma_tf32(float& c0, float& c1, float& c2, float& c3,
                                         uint32_t a0, uint32_t a1, uint32_t a2, uint32_t a3,
                                         uint32_t b0, uint32_t b1) {
    asm volatile(
        "mma.sync.aligned.m16n8k8.row.col.f32.tf32.tf32.f32 "
        "{%0,%1,%2,%3}, {%4,%5,%6,%7}, {%8,%9}, {%0,%1,%2,%3};"
        : "+f"(c0), "+f"(c1), "+f"(c2), "+f"(c3)
        : "r"(a0), "r"(a1), "r"(a2), "r"(a3), "r"(b0), "r"(b1));
}

struct Frag { float c[2][8][4]; };

// ---------------------------------------------------------------------------
// cp.async producer: one 128x32 fp32 chunk of each operand into given stage.
// GMEM data is already tf32-rounded, so raw byte copies preserve numerics.
// ---------------------------------------------------------------------------
__device__ __forceinline__ void issue_chunk(const float* __restrict__ A, int lda,
                                            const float* __restrict__ Bp, int ldb,
                                            int k0, uint32_t sA, uint32_t sB) {
    int tid = threadIdx.x;
    int row = tid >> 3, f4 = tid & 7;
#pragma unroll
    for (int p = 0; p < 4; p++) {
        int r = row + p * 32;
        const float* ga = A + (size_t)r * lda + k0 + f4 * 4;
        const float* gb = Bp + (size_t)r * ldb + k0 + f4 * 4;
        uint32_t da = sA + (uint32_t)(r * LDS_ + f4 * 4) * 4u;
        uint32_t db = sB + (uint32_t)(r * LDS_ + f4 * 4) * 4u;
        asm volatile("cp.async.cg.shared.global [%0], [%1], 16;" :: "r"(da), "l"(ga));
        asm volatile("cp.async.cg.shared.global [%0], [%1], 16;" :: "r"(db), "l"(gb));
    }
    asm volatile("cp.async.commit_group;" ::: "memory");
}

// ---------------------------------------------------------------------------
// MMA consumer for one staged chunk.
// ---------------------------------------------------------------------------
__device__ __forceinline__ void compute_chunk(const uint32_t* __restrict__ sA,
                                              const uint32_t* __restrict__ sB,
                                              Frag& fr) {
    int tid = threadIdx.x, wid = tid >> 5, lane = tid & 31;
    int wr = (wid >> 1) * 32;
    int wc = (wid & 1) * 64;
    int g = lane >> 2, tg = lane & 3;

#pragma unroll
    for (int ks = 0; ks < 4; ks++) {
        int kc = ks * 8;
        uint32_t a[2][4];
#pragma unroll
        for (int m = 0; m < 2; m++) {
            int r0 = wr + m * 16 + g;
            a[m][0] = sA[r0 * LDS_ + kc + tg];
            a[m][1] = sA[(r0 + 8) * LDS_ + kc + tg];
            a[m][2] = sA[r0 * LDS_ + kc + tg + 4];
            a[m][3] = sA[(r0 + 8) * LDS_ + kc + tg + 4];
        }
#pragma unroll
        for (int n = 0; n < 8; n++) {
            int cn = wc + n * 8 + g;
            uint32_t b0 = sB[cn * LDS_ + kc + tg];
            uint32_t b1 = sB[cn * LDS_ + kc + tg + 4];
#pragma unroll
            for (int m = 0; m < 2; m++)
                mma_tf32(fr.c[m][n][0], fr.c[m][n][1], fr.c[m][n][2], fr.c[m][n][3],
                         a[m][0], a[m][1], a[m][2], a[m][3], b0, b1);
        }
    }
}

// ---------------------------------------------------------------------------
// 3-stage pipelined GEMM mainloop: C(128x128) += A(128xK) * B(128xK)^T.
// One __syncthreads per chunk; prefetch depth 2.
// ---------------------------------------------------------------------------
__device__ __forceinline__ void run_gemm(const float* __restrict__ A, int lda,
                                         const float* __restrict__ Bp, int ldb,
                                         int nchunks, uint32_t* sm, Frag& fr) {
#pragma unroll
    for (int m = 0; m < 2; m++)
#pragma unroll
        for (int n = 0; n < 8; n++)
#pragma unroll
            for (int q = 0; q < 4; q++) fr.c[m][n][q] = 0.f;

    uint32_t sbase = (uint32_t)__cvta_generic_to_shared(sm);
    uint32_t stA[NSTAGE], stB[NSTAGE];
    const uint32_t* cA[NSTAGE];
    const uint32_t* cB[NSTAGE];
#pragma unroll
    for (int s = 0; s < NSTAGE; s++) {
        stA[s] = sbase + (uint32_t)(2 * s) * TILE_FLOATS * 4u;
        stB[s] = sbase + (uint32_t)(2 * s + 1) * TILE_FLOATS * 4u;
        cA[s] = sm + (size_t)(2 * s) * TILE_FLOATS;
        cB[s] = sm + (size_t)(2 * s + 1) * TILE_FLOATS;
    }

    issue_chunk(A, lda, Bp, ldb, 0, stA[0], stB[0]);
    if (nchunks > 1) issue_chunk(A, lda, Bp, ldb, KC, stA[1], stB[1]);

    int s = 0;
    for (int c = 0; c < nchunks; c++) {
        if (c + 1 < nchunks)
            asm volatile("cp.async.wait_group 1;" ::: "memory");
        else
            asm volatile("cp.async.wait_group 0;" ::: "memory");
        __syncthreads();
        if (c + 2 < nchunks) {
            int ns = s + 2; if (ns >= NSTAGE) ns -= NSTAGE;
            issue_chunk(A, lda, Bp, ldb, (c + 2) * KC, stA[ns], stB[ns]);
        }
        compute_chunk(cA[s], cB[s], fr);
        if (++s == NSTAGE) s = 0;
    }
}

// ---------------------------------------------------------------------------
// Kernel 1: S[b,i,j] = Xc[b,i,:].Xc[b,j,:] / sqrt(D)  (lower-triangle tiles)
// ---------------------------------------------------------------------------
__global__ void __launch_bounds__(256) qk_mma_kernel() {
    int b = blockIdx.z;
    int i0 = blockIdx.y * 128;
    int j0 = blockIdx.x * 128;
    if (j0 > i0) return;

    extern __shared__ uint32_t sm[];
    const float* A = g_Xc + (size_t)b * T_ * D_ + (size_t)i0 * D_;
    const float* Bp = g_Xc + (size_t)b * T_ * D_ + (size_t)j0 * D_;

    Frag fr;
    run_gemm(A, D_, Bp, D_, D_ / KC, sm, fr);

    int tid = threadIdx.x, wid = tid >> 5, lane = tid & 31;
    int wr = (wid >> 1) * 32, wc = (wid & 1) * 64;
    int g = lane >> 2, tg = lane & 3;
    const float scl = 0.036084391824351615f;  // 1/sqrt(768)
    float* C = g_S + (size_t)b * T_ * T_;
#pragma unroll
    for (int m = 0; m < 2; m++) {
        int r0 = i0 + wr + m * 16 + g;
#pragma unroll
        for (int n = 0; n < 8; n++) {
            int cc = j0 + wc + n * 8 + tg * 2;
            float2 v0 = make_float2(fr.c[m][n][0] * scl, fr.c[m][n][1] * scl);
            float2 v1 = make_float2(fr.c[m][n][2] * scl, fr.c[m][n][3] * scl);
            *(float2*)(C + (size_t)r0 * T_ + cc) = v0;
            *(float2*)(C + (size_t)(r0 + 8) * T_ + cc) = v1;
        }
    }
}

// ---------------------------------------------------------------------------
// Kernel 2: in-place causal softmax + post-softmax sit_mask zeroing.
// Weights are tf32-rounded at the store so pv can cp.async raw bytes.
// ---------------------------------------------------------------------------
__global__ __launch_bounds__(256) void softmax_kernel(const float* __restrict__ mask) {
    int row = blockIdx.x;
    int b = row >> 11;
    int i = row & (T_ - 1);
    float* srow = g_S + (size_t)b * T_ * T_ + (size_t)i * T_;
    const float* mrow = mask + (size_t)b * T_;
    int tid = threadIdx.x;

    __shared__ float sh[T_];
    __shared__ float red[8];

    if (mrow[i] == 0.0f) {
        float4 z = make_float4(0.f, 0.f, 0.f, 0.f);
        for (int j4 = tid; j4 < T_ / 4; j4 += 256) ((float4*)srow)[j4] = z;
        return;
    }

    int n = i + 1;
    float lm = -3.4e38f;
    for (int j = tid; j < n; j += 256) { float v = srow[j]; sh[j] = v; lm = fmaxf(lm, v); }
#pragma unroll
    for (int o = 16; o > 0; o >>= 1) lm = fmaxf(lm, __shfl_xor_sync(0xffffffffu, lm, o));
    if ((tid & 31) == 0) red[tid >> 5] = lm;
    __syncthreads();
    float m = red[0];
#pragma unroll
    for (int k = 1; k < 8; k++) m = fmaxf(m, red[k]);
    __syncthreads();

    float ls = 0.f;
    for (int j = tid; j < n; j += 256) ls += __expf(sh[j] - m);
#pragma unroll
    for (int o = 16; o > 0; o >>= 1) ls += __shfl_xor_sync(0xffffffffu, ls, o);
    if ((tid & 31) == 0) red[tid >> 5] = ls;
    __syncthreads();
    float l = red[0];
#pragma unroll
    for (int k = 1; k < 8; k++) l += red[k];
    float inv = 1.0f / l;

    for (int j = tid; j < T_; j += 256) {
        float w = 0.f;
        if (j < n && mrow[j] != 0.f) w = __expf(sh[j] - m) * inv;
        srow[j] = __uint_as_float(f2tf32(w));
    }
}

// ---------------------------------------------------------------------------
// Kernel 2.5: Xt[b,d,j] = tf32(X[b,j,d]); Xc[b,j,d] = tf32(X[b,j,d]);
//             out[b,j,D+d] = X[b,j,d]  (concat half, unconverted)
// ---------------------------------------------------------------------------
__global__ __launch_bounds__(256) void transpose_concat_kernel(const float* __restrict__ X,
                                                               float* __restrict__ out) {
    __shared__ float t[32][33];
    int b = blockIdx.z, j0 = blockIdx.x * 32, d0 = blockIdx.y * 32;
    int tx = threadIdx.x, ty = threadIdx.y;
    const float* Xb = X + (size_t)b * T_ * D_;
    float* Xc = g_Xc + (size_t)b * T_ * D_;
#pragma unroll
    for (int r = 0; r < 32; r += 8) {
        float v = Xb[(size_t)(j0 + ty + r) * D_ + d0 + tx];
        float vt = __uint_as_float(f2tf32(v));
        t[ty + r][tx] = vt;
        out[((size_t)b * T_ + j0 + ty + r) * (2 * D_) + D_ + d0 + tx] = v;
        Xc[(size_t)(j0 + ty + r) * D_ + d0 + tx] = vt;
    }
    __syncthreads();
    float* Xt = g_Xt + (size_t)b * D_ * T_;
#pragma unroll
    for (int r = 0; r < 32; r += 8)
        Xt[(size_t)(d0 + ty + r) * T_ + j0 + tx] = t[tx][ty + r];
}

// ---------------------------------------------------------------------------
// Kernel 3: out[b,i,d] = sum_j W[b,i,j]*Xt[b,d,j]  (K truncated at i0+128).
// i-tiles mapped in DESCENDING K order so long-K CTAs launch first (wave LB).
// ---------------------------------------------------------------------------
__global__ void __launch_bounds__(256) pv_mma_kernel(float* __restrict__ out) {
    int b = blockIdx.z;
    int i0 = (gridDim.y - 1 - blockIdx.y) * 128;   // big K first
    int d0 = blockIdx.x * 128;

    extern __shared__ uint32_t sm[];
    const float* A = g_S + (size_t)b * T_ * T_ + (size_t)i0 * T_;
    const float* Bp = g_Xt + (size_t)b * D_ * T_ + (size_t)d0 * T_;

    Frag fr;
    run_gemm(A, T_, Bp, T_, (i0 + 128) / KC, sm, fr);

    int tid = threadIdx.x, wid = tid >> 5, lane = tid & 31;
    int wr = (wid >> 1) * 32, wc = (wid & 1) * 64;
    int g = lane >> 2, tg = lane & 3;
#pragma unroll
    for (int m = 0; m < 2; m++) {
        int r0 = i0 + wr + m * 16 + g;
#pragma unroll
        for (int n = 0; n < 8; n++) {
            int cc = d0 + wc + n * 8 + tg * 2;
            float2 v0 = make_float2(fr.c[m][n][0], fr.c[m][n][1]);
            float2 v1 = make_float2(fr.c[m][n][2], fr.c[m][n][3]);
            *(float2*)(out + ((size_t)b * T_ + r0) * (2 * D_) + cc) = v0;
            *(float2*)(out + ((size_t)b * T_ + r0 + 8) * (2 * D_) + cc) = v1;
        }
    }
}

extern "C" void kernel_launch(void* const* d_in, const int* in_sizes, int n_in,
                              void* d_out, int out_size) {
    const float* X = (const float*)d_in[0];
    const float* mask = (const float*)d_in[1];
    // d_in[2] (proposition_matrix) is unused by the reference computation.
    float* out = (float*)d_out;

    cudaFuncSetAttribute(qk_mma_kernel, cudaFuncAttributeMaxDynamicSharedMemorySize, SMEM_DYN);
    cudaFuncSetAttribute(pv_mma_kernel, cudaFuncAttributeMaxDynamicSharedMemorySize, SMEM_DYN);

    dim3 gt(T_ / 32, D_ / 32, B_);
    transpose_concat_kernel<<<gt, dim3(32, 8)>>>(X, out);

    dim3 g1(T_ / 128, T_ / 128, B_);
    qk_mma_kernel<<<g1, 256, SMEM_DYN>>>();

    softmax_kernel<<<B_ * T_, 256>>>(mask);

    dim3 g3(D_ / 128, T_ / 128, B_);
    pv_mma_kernel<<<g3, 256, SMEM_DYN>>>(out);
}